// round 1
// baseline (speedup 1.0000x reference)
#include <cuda_runtime.h>
#include <math.h>

#define BB 32
#define NN 1000
#define CC 1601
#define HIDD 64
#define MM (BB*NN)          // 32000
#define TAKE_K 64
#define NBLK1 245           // ceil(1e6 / 4096)
#define CAND1 (NBLK1*64)    // 15680

// ---------------- device scratch (static, no allocs) ----------------
__device__ float g_H[(size_t)MM * 128];     // hidden: cols 0-63 subj, 64-127 obj
__device__ float g_SO[(size_t)MM * 128];    // cols 0-63 = S, 64-127 = O
__device__ float g_D[(size_t)BB * NN * NN]; // raw dot products (pre-sigmoid)
__device__ unsigned long long g_c1[(size_t)BB * CAND1];
__device__ unsigned long long g_c2[(size_t)BB * 256];

// ---------------- GEMM1: H = relu(X @ [Ws1|Wo1] + [bs1|bo1]) ----------------
// X: [32000, 1601], output H: [32000, 128]
__global__ void __launch_bounds__(256) k_gemm1(
    const float* __restrict__ X,
    const float* __restrict__ Ws1, const float* __restrict__ bs1,
    const float* __restrict__ Wo1, const float* __restrict__ bo1)
{
    __shared__ float As[16][128];
    __shared__ float Bs[16][128];

    const int tid = threadIdx.x;
    const int row0 = blockIdx.x * 128;
    const int tm = tid >> 4;        // 0..15
    const int tn = tid & 15;        // 0..15

    const int arow = tid >> 1;          // 0..127
    const int aseg = (tid & 1) * 8;     // 0 or 8
    const float* xrow = X + (size_t)(row0 + arow) * CC;

    float acc[8][8];
#pragma unroll
    for (int i = 0; i < 8; i++)
#pragma unroll
        for (int j = 0; j < 8; j++) acc[i][j] = 0.f;

    for (int k0 = 0; k0 < CC; k0 += 16) {
        // load A tile (zero-padded at K tail)
#pragma unroll
        for (int i = 0; i < 8; i++) {
            int kk = aseg + i;
            float v = (k0 + kk < CC) ? xrow[k0 + kk] : 0.f;
            As[kk][arow] = v;
        }
        // load B tile: cols 0-63 from Ws1, 64-127 from Wo1
#pragma unroll
        for (int i = 0; i < 8; i++) {
            int idx = tid + i * 256;
            int kk = idx >> 7;
            int cc = idx & 127;
            int k = k0 + kk;
            float v = 0.f;
            if (k < CC) v = (cc < 64) ? Ws1[k * 64 + cc] : Wo1[k * 64 + (cc - 64)];
            Bs[kk][cc] = v;
        }
        __syncthreads();

#pragma unroll
        for (int kk = 0; kk < 16; kk++) {
            float4 a0 = *(const float4*)(&As[kk][tm * 8]);
            float4 a1 = *(const float4*)(&As[kk][tm * 8 + 4]);
            float4 b0 = *(const float4*)(&Bs[kk][tn * 8]);
            float4 b1 = *(const float4*)(&Bs[kk][tn * 8 + 4]);
            float a[8] = {a0.x, a0.y, a0.z, a0.w, a1.x, a1.y, a1.z, a1.w};
            float b[8] = {b0.x, b0.y, b0.z, b0.w, b1.x, b1.y, b1.z, b1.w};
#pragma unroll
            for (int i = 0; i < 8; i++)
#pragma unroll
                for (int j = 0; j < 8; j++)
                    acc[i][j] = fmaf(a[i], b[j], acc[i][j]);
        }
        __syncthreads();
    }

#pragma unroll
    for (int j = 0; j < 8; j++) {
        int col = tn * 8 + j;
        float bias = (col < 64) ? bs1[col] : bo1[col - 64];
#pragma unroll
        for (int i = 0; i < 8; i++) {
            float v = acc[i][j] + bias;
            g_H[(size_t)(row0 + tm * 8 + i) * 128 + col] = fmaxf(v, 0.f);
        }
    }
}

// ---------------- GEMM2: S = H[:, :64]@Ws2+bs2 ; O = H[:, 64:]@Wo2+bo2 ----------------
__global__ void __launch_bounds__(256) k_gemm2(
    const float* __restrict__ Ws2, const float* __restrict__ bs2,
    const float* __restrict__ Wo2, const float* __restrict__ bo2)
{
    __shared__ float Hs[16][128];
    __shared__ float W[2][64][64];   // [half][h][j]

    const int tid = threadIdx.x;
    const int r0 = blockIdx.x * 16;

    float* wflat = &W[0][0][0];
    for (int i = tid; i < 4096; i += 256) {
        wflat[i] = Ws2[i];
        wflat[4096 + i] = Wo2[i];
    }
    for (int i = tid; i < 2048; i += 256)
        Hs[i >> 7][i & 127] = g_H[(size_t)r0 * 128 + i];
    __syncthreads();

    const int col = tid & 127;
    const int rb = tid >> 7;        // 0 or 1
    const int half = col >> 6;
    const int jj = col & 63;

    float acc[8];
#pragma unroll
    for (int i = 0; i < 8; i++) acc[i] = 0.f;

    const float* w = &W[half][0][jj];
    const int hbase = half * 64;
#pragma unroll
    for (int h = 0; h < 64; h++) {
        float wv = w[h * 64];
#pragma unroll
        for (int i = 0; i < 8; i++)
            acc[i] = fmaf(Hs[rb + 2 * i][hbase + h], wv, acc[i]);
    }
    float bias = half ? bo2[jj] : bs2[jj];
#pragma unroll
    for (int i = 0; i < 8; i++)
        g_SO[(size_t)(r0 + rb + 2 * i) * 128 + col] = acc[i] + bias;
}

// ---------------- Score GEMM: D[b,i,j] = S[b,i,:] . O[b,j,:] ----------------
__global__ void __launch_bounds__(256) k_score()
{
    __shared__ float Ss[64][68];   // [d][ii], padded stride (16B-aligned rows)
    __shared__ float Os[64][68];   // [d][jj]

    const int tid = threadIdx.x;
    const int b  = blockIdx.z;
    const int i0 = blockIdx.y * 64;
    const int j0 = blockIdx.x * 64;

    for (int e = tid; e < 4096; e += 256) {
        int ii = e >> 6;
        int d  = e & 63;
        int gi = i0 + ii;
        int gj = j0 + ii;
        float sv = 0.f, ov = 0.f;
        if (gi < NN) sv = g_SO[((size_t)(b * NN + gi)) * 128 + d];
        if (gj < NN) ov = g_SO[((size_t)(b * NN + gj)) * 128 + 64 + d];
        Ss[d][ii] = sv;
        Os[d][ii] = ov;
    }
    __syncthreads();

    const int tm = tid >> 4;
    const int tn = tid & 15;

    float acc[4][4];
#pragma unroll
    for (int i = 0; i < 4; i++)
#pragma unroll
        for (int j = 0; j < 4; j++) acc[i][j] = 0.f;

#pragma unroll 4
    for (int kk = 0; kk < 64; kk++) {
        float4 av = *(const float4*)(&Ss[kk][tm * 4]);
        float4 bv = *(const float4*)(&Os[kk][tn * 4]);
        float a[4] = {av.x, av.y, av.z, av.w};
        float bb[4] = {bv.x, bv.y, bv.z, bv.w};
#pragma unroll
        for (int i = 0; i < 4; i++)
#pragma unroll
            for (int j = 0; j < 4; j++)
                acc[i][j] = fmaf(a[i], bb[j], acc[i][j]);
    }

#pragma unroll
    for (int i = 0; i < 4; i++) {
        int gi = i0 + tm * 4 + i;
        if (gi >= NN) continue;
#pragma unroll
        for (int j = 0; j < 4; j++) {
            int gj = j0 + tn * 4 + j;
            if (gj < NN)
                g_D[((size_t)b * NN + gi) * NN + gj] = acc[i][j];
        }
    }
}

// ---------------- bitonic sort (descending) on smem u64 keys ----------------
template <int NTOT, int NTHR>
__device__ __forceinline__ void bitonic_desc(unsigned long long* k)
{
    for (int size = 2; size <= NTOT; size <<= 1) {
        for (int stride = size >> 1; stride > 0; stride >>= 1) {
            __syncthreads();
            for (int e = threadIdx.x; e < NTOT / 2; e += NTHR) {
                int i = 2 * e - (e & (stride - 1));
                int j = i + stride;
                bool up = ((i & size) == 0);
                unsigned long long a = k[i], b = k[j];
                bool sw = up ? (a < b) : (a > b);
                if (sw) { k[i] = b; k[j] = a; }
            }
        }
    }
    __syncthreads();
}

__device__ __forceinline__ unsigned long long pack_key(float s, unsigned flat)
{
    unsigned u = __float_as_uint(s);
    u = (u & 0x80000000u) ? ~u : (u | 0x80000000u);
    return (((unsigned long long)u) << 32) | (unsigned)(0xFFFFFFFFu - flat);
}

// stage 1: per-4096-chunk top-64 (sigmoid applied here; ranking = reference ranking)
__global__ void __launch_bounds__(256) k_top1()
{
    __shared__ unsigned long long keys[4096];
    const int tid = threadIdx.x;
    const int b = blockIdx.y;
    const int blk = blockIdx.x;
    const size_t base = (size_t)blk * 4096;
    const float* Db = g_D + (size_t)b * NN * NN;

#pragma unroll
    for (int i = 0; i < 16; i++) {
        int e = tid + i * 256;
        size_t flat = base + e;
        unsigned long long key = 0ull;
        if (flat < (size_t)NN * NN) {
            float v = Db[flat];
            float s = 1.f / (1.f + expf(-v));
            key = pack_key(s, (unsigned)flat);
        }
        keys[e] = key;
    }
    bitonic_desc<4096, 256>(keys);
    if (tid < 64)
        g_c1[(size_t)b * CAND1 + blk * 64 + tid] = keys[tid];
}

// stage 2: 4 groups of 4096 candidates -> top-64 each
__global__ void __launch_bounds__(256) k_top2()
{
    __shared__ unsigned long long keys[4096];
    const int tid = threadIdx.x;
    const int b = blockIdx.y;
    const int g = blockIdx.x;
    const int base = g * 4096;

#pragma unroll
    for (int i = 0; i < 16; i++) {
        int e = tid + i * 256;
        int idx = base + e;
        keys[e] = (idx < CAND1) ? g_c1[(size_t)b * CAND1 + idx] : 0ull;
    }
    bitonic_desc<4096, 256>(keys);
    if (tid < 64)
        g_c2[(size_t)b * 256 + g * 64 + tid] = keys[tid];
}

// stage 3: final 256 -> 64, unpack, write output
__global__ void __launch_bounds__(256) k_top3(float* __restrict__ out)
{
    __shared__ unsigned long long keys[256];
    const int tid = threadIdx.x;
    const int b = blockIdx.x;

    keys[tid] = g_c2[(size_t)b * 256 + tid];
    bitonic_desc<256, 256>(keys);

    if (tid < 64) {
        unsigned long long key = keys[tid];
        unsigned u = (unsigned)(key >> 32);
        unsigned low = (unsigned)key;
        unsigned flat = 0xFFFFFFFFu - low;
        unsigned bits = (u & 0x80000000u) ? (u ^ 0x80000000u) : ~u;
        float s = __uint_as_float(bits);
        int subj = flat / NN;
        int obj = flat % NN;
        out[(b * TAKE_K + tid) * 2 + 0] = (float)subj;
        out[(b * TAKE_K + tid) * 2 + 1] = (float)obj;
        out[BB * TAKE_K * 2 + b * TAKE_K + tid] = s;
    }
}

// ---------------- launch ----------------
extern "C" void kernel_launch(void* const* d_in, const int* in_sizes, int n_in,
                              void* d_out, int out_size)
{
    const float* X   = (const float*)d_in[0];   // class_logits [32,1000,1601]
    // d_in[1] = proposals (unused)
    const float* Ws1 = (const float*)d_in[2];
    const float* bs1 = (const float*)d_in[3];
    const float* Ws2 = (const float*)d_in[4];
    const float* bs2 = (const float*)d_in[5];
    const float* Wo1 = (const float*)d_in[6];
    const float* bo1 = (const float*)d_in[7];
    const float* Wo2 = (const float*)d_in[8];
    const float* bo2 = (const float*)d_in[9];
    float* out = (float*)d_out;

    k_gemm1<<<MM / 128, 256>>>(X, Ws1, bs1, Wo1, bo1);
    k_gemm2<<<MM / 16, 256>>>(Ws2, bs2, Wo2, bo2);
    k_score<<<dim3(16, 16, BB), 256>>>();
    k_top1<<<dim3(NBLK1, BB), 256>>>();
    k_top2<<<dim3(4, BB), 256>>>();
    k_top3<<<BB, 256>>>(out);
}

// round 2
// speedup vs baseline: 1.9509x; 1.9509x over previous
#include <cuda_runtime.h>
#include <math.h>

#define BB 32
#define NN 1000
#define CC 1601
#define MM (BB*NN)          // 32000
#define TAKE_K 64
#define CAP 4096            // candidate capacity per batch

// ---------------- device scratch (static, no allocs) ----------------
__device__ float g_H[(size_t)MM * 128];     // hidden: cols 0-63 subj, 64-127 obj
__device__ float g_SO[(size_t)MM * 128];    // cols 0-63 = S, 64-127 = O
__device__ float g_D[(size_t)BB * NN * NN]; // raw dot products (pre-sigmoid)
__device__ unsigned g_cnt1[BB * 4096];
__device__ unsigned g_cnt2[BB * 4096];
__device__ unsigned g_ccnt[BB];
__device__ int      g_b1[BB];
__device__ unsigned g_cntgt1[BB];
__device__ int      g_b2[BB];
__device__ unsigned long long g_cand[(size_t)BB * CAP];

// ---------------- helpers ----------------
__device__ __forceinline__ unsigned long long pack_key(float s, unsigned flat)
{
    unsigned u = __float_as_uint(s);
    u = (u & 0x80000000u) ? ~u : (u | 0x80000000u);
    return (((unsigned long long)u) << 32) | (unsigned)(0xFFFFFFFFu - flat);
}

__device__ __forceinline__ float sigmoidf_dev(float v)
{
    return 1.f / (1.f + expf(-v));
}

// ---------------- GEMM1: H = relu(X @ [Ws1|Wo1] + [bs1|bo1]) ----------------
__global__ void __launch_bounds__(256) k_gemm1(
    const float* __restrict__ X,
    const float* __restrict__ Ws1, const float* __restrict__ bs1,
    const float* __restrict__ Wo1, const float* __restrict__ bo1)
{
    __shared__ float As[16][128];
    __shared__ float Bs[16][128];

    const int tid = threadIdx.x;
    const int row0 = blockIdx.x * 128;
    const int tm = tid >> 4;
    const int tn = tid & 15;

    const int arow = tid >> 1;
    const int aseg = (tid & 1) * 8;
    const float* xrow = X + (size_t)(row0 + arow) * CC;

    float acc[8][8];
#pragma unroll
    for (int i = 0; i < 8; i++)
#pragma unroll
        for (int j = 0; j < 8; j++) acc[i][j] = 0.f;

    for (int k0 = 0; k0 < CC; k0 += 16) {
#pragma unroll
        for (int i = 0; i < 8; i++) {
            int kk = aseg + i;
            float v = (k0 + kk < CC) ? xrow[k0 + kk] : 0.f;
            As[kk][arow] = v;
        }
#pragma unroll
        for (int i = 0; i < 8; i++) {
            int idx = tid + i * 256;
            int kk = idx >> 7;
            int cc = idx & 127;
            int k = k0 + kk;
            float v = 0.f;
            if (k < CC) v = (cc < 64) ? Ws1[k * 64 + cc] : Wo1[k * 64 + (cc - 64)];
            Bs[kk][cc] = v;
        }
        __syncthreads();

#pragma unroll
        for (int kk = 0; kk < 16; kk++) {
            float4 a0 = *(const float4*)(&As[kk][tm * 8]);
            float4 a1 = *(const float4*)(&As[kk][tm * 8 + 4]);
            float4 b0 = *(const float4*)(&Bs[kk][tn * 8]);
            float4 b1 = *(const float4*)(&Bs[kk][tn * 8 + 4]);
            float a[8] = {a0.x, a0.y, a0.z, a0.w, a1.x, a1.y, a1.z, a1.w};
            float b[8] = {b0.x, b0.y, b0.z, b0.w, b1.x, b1.y, b1.z, b1.w};
#pragma unroll
            for (int i = 0; i < 8; i++)
#pragma unroll
                for (int j = 0; j < 8; j++)
                    acc[i][j] = fmaf(a[i], b[j], acc[i][j]);
        }
        __syncthreads();
    }

#pragma unroll
    for (int j = 0; j < 8; j++) {
        int col = tn * 8 + j;
        float bias = (col < 64) ? bs1[col] : bo1[col - 64];
#pragma unroll
        for (int i = 0; i < 8; i++) {
            float v = acc[i][j] + bias;
            g_H[(size_t)(row0 + tm * 8 + i) * 128 + col] = fmaxf(v, 0.f);
        }
    }
}

// ---------------- GEMM2 ----------------
__global__ void __launch_bounds__(256) k_gemm2(
    const float* __restrict__ Ws2, const float* __restrict__ bs2,
    const float* __restrict__ Wo2, const float* __restrict__ bo2)
{
    __shared__ float Hs[16][128];
    __shared__ float W[2][64][64];

    const int tid = threadIdx.x;
    const int r0 = blockIdx.x * 16;

    float* wflat = &W[0][0][0];
    for (int i = tid; i < 4096; i += 256) {
        wflat[i] = Ws2[i];
        wflat[4096 + i] = Wo2[i];
    }
    for (int i = tid; i < 2048; i += 256)
        Hs[i >> 7][i & 127] = g_H[(size_t)r0 * 128 + i];
    __syncthreads();

    const int col = tid & 127;
    const int rb = tid >> 7;
    const int half = col >> 6;
    const int jj = col & 63;

    float acc[8];
#pragma unroll
    for (int i = 0; i < 8; i++) acc[i] = 0.f;

    const float* w = &W[half][0][jj];
    const int hbase = half * 64;
#pragma unroll
    for (int h = 0; h < 64; h++) {
        float wv = w[h * 64];
#pragma unroll
        for (int i = 0; i < 8; i++)
            acc[i] = fmaf(Hs[rb + 2 * i][hbase + h], wv, acc[i]);
    }
    float bias = half ? bo2[jj] : bs2[jj];
#pragma unroll
    for (int i = 0; i < 8; i++)
        g_SO[(size_t)(r0 + rb + 2 * i) * 128 + col] = acc[i] + bias;
}

// ---------------- Score GEMM (128x128 tiles) + fused level-1 histogram ----------------
__global__ void __launch_bounds__(256) k_score()
{
    extern __shared__ float sm[];
    float (*Ss)[132] = (float(*)[132])sm;                 // [64][132]
    float (*Os)[132] = (float(*)[132])(sm + 64 * 132);    // [64][132]
    unsigned* hist = (unsigned*)(sm + 2 * 64 * 132);      // [4096]

    const int tid = threadIdx.x;
    const int b  = blockIdx.z;
    const int i0 = blockIdx.y * 128;
    const int j0 = blockIdx.x * 128;

    for (int h = tid; h < 4096; h += 256) hist[h] = 0;

    for (int e = tid; e < 8192; e += 256) {
        int ii = e >> 6;
        int d  = e & 63;
        int gi = i0 + ii;
        int gj = j0 + ii;
        Ss[d][ii] = (gi < NN) ? g_SO[((size_t)(b * NN + gi)) * 128 + d]      : 0.f;
        Os[d][ii] = (gj < NN) ? g_SO[((size_t)(b * NN + gj)) * 128 + 64 + d] : 0.f;
    }
    __syncthreads();

    const int tm = tid >> 4;
    const int tn = tid & 15;

    float acc[8][8];
#pragma unroll
    for (int i = 0; i < 8; i++)
#pragma unroll
        for (int j = 0; j < 8; j++) acc[i][j] = 0.f;

#pragma unroll 4
    for (int kk = 0; kk < 64; kk++) {
        float4 a0 = *(const float4*)(&Ss[kk][tm * 8]);
        float4 a1 = *(const float4*)(&Ss[kk][tm * 8 + 4]);
        float4 b0 = *(const float4*)(&Os[kk][tn * 8]);
        float4 b1 = *(const float4*)(&Os[kk][tn * 8 + 4]);
        float a[8] = {a0.x, a0.y, a0.z, a0.w, a1.x, a1.y, a1.z, a1.w};
        float bb2[8] = {b0.x, b0.y, b0.z, b0.w, b1.x, b1.y, b1.z, b1.w};
#pragma unroll
        for (int i = 0; i < 8; i++)
#pragma unroll
            for (int j = 0; j < 8; j++)
                acc[i][j] = fmaf(a[i], bb2[j], acc[i][j]);
    }

    const int gj0 = j0 + tn * 8;
#pragma unroll
    for (int i = 0; i < 8; i++) {
        int gi = i0 + tm * 8 + i;
        if (gi >= NN) continue;
        float* drow = g_D + ((size_t)b * NN + gi) * NN;
        if (gj0 + 7 < NN) {
            *(float4*)(drow + gj0)     = make_float4(acc[i][0], acc[i][1], acc[i][2], acc[i][3]);
            *(float4*)(drow + gj0 + 4) = make_float4(acc[i][4], acc[i][5], acc[i][6], acc[i][7]);
#pragma unroll
            for (int j = 0; j < 8; j++) {
                float s = sigmoidf_dev(acc[i][j]);
                unsigned m = __float_as_uint(s) | 0x80000000u;
                atomicAdd(&hist[(m >> 19) & 0xFFF], 1u);
            }
        } else {
#pragma unroll
            for (int j = 0; j < 8; j++) {
                int gj = gj0 + j;
                if (gj < NN) {
                    drow[gj] = acc[i][j];
                    float s = sigmoidf_dev(acc[i][j]);
                    unsigned m = __float_as_uint(s) | 0x80000000u;
                    atomicAdd(&hist[(m >> 19) & 0xFFF], 1u);
                }
            }
        }
    }
    __syncthreads();
    for (int h = tid; h < 4096; h += 256) {
        unsigned c = hist[h];
        if (c) atomicAdd(&g_cnt1[b * 4096 + h], c);
    }
}

// ---------------- threshold finder (descending cumulative over 4096 bins) ----------------
__device__ void find_thresh(const unsigned* __restrict__ hist, unsigned K,
                            int* out_bin, unsigned* out_above)
{
    __shared__ unsigned seg[256];
    __shared__ unsigned scan[256];
    const int t = threadIdx.x;

    unsigned s = 0;
#pragma unroll
    for (int q = 0; q < 16; q++) s += hist[4095 - (t * 16 + q)];
    seg[t] = s;
    scan[t] = s;
    __syncthreads();
    for (int off = 1; off < 256; off <<= 1) {
        unsigned v = (t >= off) ? scan[t - off] : 0u;
        __syncthreads();
        scan[t] += v;
        __syncthreads();
    }
    unsigned inc = scan[t];
    unsigned exc = inc - seg[t];
    if (exc < K && inc >= K) {
        unsigned cum = exc;
        for (int q = 0; q < 16; q++) {
            int bin = 4095 - (t * 16 + q);
            unsigned c = hist[bin];
            if (cum + c >= K) { *out_bin = bin; *out_above = cum; break; }
            cum += c;
        }
    }
}

__global__ void __launch_bounds__(256) k_thresh1()
{
    int b = blockIdx.x;
    find_thresh(g_cnt1 + b * 4096, 64u, &g_b1[b], &g_cntgt1[b]);
}

__global__ void __launch_bounds__(256) k_thresh2()
{
    int b = blockIdx.x;
    __shared__ int dummy_bin;
    __shared__ unsigned dummy_above;
    unsigned K = 64u - g_cntgt1[b];
    find_thresh(g_cnt2 + b * 4096, K, &g_b2[b], &dummy_above);
    (void)dummy_bin;
}

// ---------------- pass 2: compact bin1>b1, histogram level-2 for bin1==b1 ----------------
__global__ void __launch_bounds__(256) k_pass2()
{
    __shared__ unsigned hist[4096];
    const int b = blockIdx.y;
    const int B1 = g_b1[b];
    for (int h = threadIdx.x; h < 4096; h += 256) hist[h] = 0;
    __syncthreads();

    const float* Db = g_D + (size_t)b * NN * NN;
    const int start = blockIdx.x * 15625;
    for (int e = start + threadIdx.x; e < start + 15625; e += 256) {
        float v = Db[e];
        float s = sigmoidf_dev(v);
        unsigned m = __float_as_uint(s) | 0x80000000u;
        int bin1 = (m >> 19) & 0xFFF;
        if (bin1 > B1) {
            unsigned idx = atomicAdd(&g_ccnt[b], 1u);
            if (idx < CAP) g_cand[(size_t)b * CAP + idx] = pack_key(s, (unsigned)e);
        } else if (bin1 == B1) {
            atomicAdd(&hist[(m >> 7) & 0xFFF], 1u);
        }
    }
    __syncthreads();
    for (int h = threadIdx.x; h < 4096; h += 256) {
        unsigned c = hist[h];
        if (c) atomicAdd(&g_cnt2[b * 4096 + h], c);
    }
}

// ---------------- pass 3: compact bin1==b1 && bin2>=b2 ----------------
__global__ void __launch_bounds__(256) k_pass3()
{
    const int b = blockIdx.y;
    const int B1 = g_b1[b];
    const int B2 = g_b2[b];
    const float* Db = g_D + (size_t)b * NN * NN;
    const int start = blockIdx.x * 15625;
    for (int e = start + threadIdx.x; e < start + 15625; e += 256) {
        float v = Db[e];
        float s = sigmoidf_dev(v);
        unsigned m = __float_as_uint(s) | 0x80000000u;
        int bin1 = (m >> 19) & 0xFFF;
        if (bin1 == B1 && (int)((m >> 7) & 0xFFF) >= B2) {
            unsigned idx = atomicAdd(&g_ccnt[b], 1u);
            if (idx < CAP) g_cand[(size_t)b * CAP + idx] = pack_key(s, (unsigned)e);
        }
    }
}

// ---------------- bitonic sort (descending) ----------------
template <int NTOT, int NTHR>
__device__ __forceinline__ void bitonic_desc(unsigned long long* k)
{
    for (int size = 2; size <= NTOT; size <<= 1) {
        for (int stride = size >> 1; stride > 0; stride >>= 1) {
            __syncthreads();
            for (int e = threadIdx.x; e < NTOT / 2; e += NTHR) {
                int i = 2 * e - (e & (stride - 1));
                int j = i + stride;
                bool up = ((i & size) == 0);
                unsigned long long a = k[i], b = k[j];
                bool sw = up ? (a < b) : (a > b);
                if (sw) { k[i] = b; k[j] = a; }
            }
        }
    }
    __syncthreads();
}

// ---------------- final sort of candidates + output ----------------
__global__ void __launch_bounds__(256) k_sort(float* __restrict__ out)
{
    __shared__ unsigned long long keys[CAP];
    const int tid = threadIdx.x;
    const int b = blockIdx.x;
    unsigned n = g_ccnt[b];
    if (n > CAP) n = CAP;

#pragma unroll
    for (int i = 0; i < CAP / 256; i++) {
        int e = tid + i * 256;
        keys[e] = (e < (int)n) ? g_cand[(size_t)b * CAP + e] : 0ull;
    }
    bitonic_desc<CAP, 256>(keys);

    if (tid < 64) {
        unsigned long long key = keys[tid];
        unsigned u = (unsigned)(key >> 32);
        unsigned low = (unsigned)key;
        unsigned flat = 0xFFFFFFFFu - low;
        unsigned bits = (u & 0x80000000u) ? (u ^ 0x80000000u) : ~u;
        float s = __uint_as_float(bits);
        int subj = flat / NN;
        int obj = flat % NN;
        out[(b * TAKE_K + tid) * 2 + 0] = (float)subj;
        out[(b * TAKE_K + tid) * 2 + 1] = (float)obj;
        out[BB * TAKE_K * 2 + b * TAKE_K + tid] = s;
    }
}

// ---------------- zero scratch counters ----------------
__global__ void k_zero()
{
    int t = blockIdx.x * blockDim.x + threadIdx.x;
    if (t < BB * 4096) { g_cnt1[t] = 0; g_cnt2[t] = 0; }
    if (t < BB) g_ccnt[t] = 0;
}

// ---------------- launch ----------------
extern "C" void kernel_launch(void* const* d_in, const int* in_sizes, int n_in,
                              void* d_out, int out_size)
{
    const float* X   = (const float*)d_in[0];
    const float* Ws1 = (const float*)d_in[2];
    const float* bs1 = (const float*)d_in[3];
    const float* Ws2 = (const float*)d_in[4];
    const float* bs2 = (const float*)d_in[5];
    const float* Wo1 = (const float*)d_in[6];
    const float* bo1 = (const float*)d_in[7];
    const float* Wo2 = (const float*)d_in[8];
    const float* bo2 = (const float*)d_in[9];
    float* out = (float*)d_out;

    const int SCORE_SMEM = (2 * 64 * 132) * 4 + 4096 * 4;  // 83968
    static int configured = 0;
    if (!configured) {
        cudaFuncSetAttribute(k_score, cudaFuncAttributeMaxDynamicSharedMemorySize, SCORE_SMEM);
        configured = 1;
    }

    k_zero<<<(BB * 4096 + 255) / 256, 256>>>();
    k_gemm1<<<MM / 128, 256>>>(X, Ws1, bs1, Wo1, bo1);
    k_gemm2<<<MM / 16, 256>>>(Ws2, bs2, Wo2, bo2);
    k_score<<<dim3(8, 8, BB), 256, SCORE_SMEM>>>();
    k_thresh1<<<BB, 256>>>();
    k_pass2<<<dim3(64, BB), 256>>>();
    k_thresh2<<<BB, 256>>>();
    k_pass3<<<dim3(64, BB), 256>>>();
    k_sort<<<BB, 256>>>(out);
}

// round 3
// speedup vs baseline: 3.6409x; 1.8662x over previous
#include <cuda_runtime.h>
#include <math.h>

#define BB 32
#define NN 1000
#define CC 1601
#define MM (BB*NN)          // 32000
#define TAKE_K 64
#define CAP 4096            // candidate capacity per batch

// ---------------- device scratch (static, no allocs) ----------------
__device__ float g_H[(size_t)MM * 128];     // hidden: cols 0-63 subj, 64-127 obj
__device__ float g_SO[(size_t)MM * 128];    // cols 0-63 = S, 64-127 = O
__device__ float g_D[(size_t)BB * NN * NN]; // raw dot products (pre-sigmoid)
__device__ unsigned g_cnt1[BB * 4096];
__device__ unsigned g_cnt2[BB * 4096];
__device__ unsigned g_ccnt[BB];
__device__ int      g_b1[BB];
__device__ unsigned g_cntgt1[BB];
__device__ int      g_b2[BB];
__device__ unsigned g_above2[BB];
__device__ unsigned long long g_cand[(size_t)BB * CAP]; // (v_bits<<32)|flat

// ---------------- helpers ----------------
// monotone map float -> unsigned (total order)
__device__ __forceinline__ unsigned flip_bits(unsigned x)
{
    return x ^ ((x & 0x80000000u) ? 0xFFFFFFFFu : 0x80000000u);
}

__device__ __forceinline__ unsigned long long pack_key(float s, unsigned flat)
{
    unsigned u = __float_as_uint(s);
    u = (u & 0x80000000u) ? ~u : (u | 0x80000000u);
    return (((unsigned long long)u) << 32) | (unsigned)(0xFFFFFFFFu - flat);
}

__device__ __forceinline__ float sigmoidf_dev(float v)
{
    return 1.f / (1.f + expf(-v));
}

__device__ __forceinline__ unsigned long long dup2(float x)
{
    unsigned long long r;
    unsigned u = __float_as_uint(x);
    asm("mov.b64 %0, {%1, %1};" : "=l"(r) : "r"(u));
    return r;
}

#define FFMA2(acc, a, b) asm("fma.rn.f32x2 %0, %1, %2, %0;" : "+l"(acc) : "l"(a), "l"(b))

// ---------------- GEMM1: H = relu(X @ [Ws1|Wo1] + [bs1|bo1]) ----------------
// 128x128 tile, 256 threads, 8x8 microtile using packed f32x2 FMA.
__global__ void __launch_bounds__(256) k_gemm1(
    const float* __restrict__ X,
    const float* __restrict__ Ws1, const float* __restrict__ bs1,
    const float* __restrict__ Wo1, const float* __restrict__ bo1)
{
    __shared__ float As[16][128];
    __shared__ float Bs[16][128];

    const int tid = threadIdx.x;
    const int row0 = blockIdx.x * 128;
    const int tm = tid >> 4;
    const int tn = tid & 15;

    const int arow = tid >> 1;
    const int aseg = (tid & 1) * 8;
    const float* xrow = X + (size_t)(row0 + arow) * CC;

    // acc2[p][j]: rows (tm*8+2p, tm*8+2p+1), col tn*8+j packed in f32x2
    unsigned long long acc2[4][8];
#pragma unroll
    for (int p = 0; p < 4; p++)
#pragma unroll
        for (int j = 0; j < 8; j++) acc2[p][j] = 0ull;

    for (int k0 = 0; k0 < CC; k0 += 16) {
#pragma unroll
        for (int i = 0; i < 8; i++) {
            int kk = aseg + i;
            float v = (k0 + kk < CC) ? xrow[k0 + kk] : 0.f;
            As[kk][arow] = v;
        }
#pragma unroll
        for (int i = 0; i < 8; i++) {
            int idx = tid + i * 256;
            int kk = idx >> 7;
            int cc = idx & 127;
            int k = k0 + kk;
            float v = 0.f;
            if (k < CC) v = (cc < 64) ? Ws1[k * 64 + cc] : Wo1[k * 64 + (cc - 64)];
            Bs[kk][cc] = v;
        }
        __syncthreads();

#pragma unroll
        for (int kk = 0; kk < 16; kk++) {
            ulonglong2 a01 = *(const ulonglong2*)(&As[kk][tm * 8]);
            ulonglong2 a23 = *(const ulonglong2*)(&As[kk][tm * 8 + 4]);
            unsigned long long ap[4] = {a01.x, a01.y, a23.x, a23.y};
            float4 b0 = *(const float4*)(&Bs[kk][tn * 8]);
            float4 b1 = *(const float4*)(&Bs[kk][tn * 8 + 4]);
            unsigned long long bd[8] = {
                dup2(b0.x), dup2(b0.y), dup2(b0.z), dup2(b0.w),
                dup2(b1.x), dup2(b1.y), dup2(b1.z), dup2(b1.w)};
#pragma unroll
            for (int p = 0; p < 4; p++)
#pragma unroll
                for (int j = 0; j < 8; j++)
                    FFMA2(acc2[p][j], ap[p], bd[j]);
        }
        __syncthreads();
    }

#pragma unroll
    for (int j = 0; j < 8; j++) {
        int col = tn * 8 + j;
        float bias = (col < 64) ? bs1[col] : bo1[col - 64];
#pragma unroll
        for (int p = 0; p < 4; p++) {
            float lo = __uint_as_float((unsigned)acc2[p][j]);
            float hi = __uint_as_float((unsigned)(acc2[p][j] >> 32));
            g_H[(size_t)(row0 + tm * 8 + 2 * p)     * 128 + col] = fmaxf(lo + bias, 0.f);
            g_H[(size_t)(row0 + tm * 8 + 2 * p + 1) * 128 + col] = fmaxf(hi + bias, 0.f);
        }
    }
}

// ---------------- GEMM2 ----------------
__global__ void __launch_bounds__(256) k_gemm2(
    const float* __restrict__ Ws2, const float* __restrict__ bs2,
    const float* __restrict__ Wo2, const float* __restrict__ bo2)
{
    __shared__ float Hs[16][128];
    __shared__ float W[2][64][64];

    const int tid = threadIdx.x;
    const int r0 = blockIdx.x * 16;

    float* wflat = &W[0][0][0];
    for (int i = tid; i < 4096; i += 256) {
        wflat[i] = Ws2[i];
        wflat[4096 + i] = Wo2[i];
    }
    for (int i = tid; i < 2048; i += 256)
        Hs[i >> 7][i & 127] = g_H[(size_t)r0 * 128 + i];
    __syncthreads();

    const int col = tid & 127;
    const int rb = tid >> 7;
    const int half = col >> 6;
    const int jj = col & 63;

    float acc[8];
#pragma unroll
    for (int i = 0; i < 8; i++) acc[i] = 0.f;

    const float* w = &W[half][0][jj];
    const int hbase = half * 64;
#pragma unroll
    for (int h = 0; h < 64; h++) {
        float wv = w[h * 64];
#pragma unroll
        for (int i = 0; i < 8; i++)
            acc[i] = fmaf(Hs[rb + 2 * i][hbase + h], wv, acc[i]);
    }
    float bias = half ? bo2[jj] : bs2[jj];
#pragma unroll
    for (int i = 0; i < 8; i++)
        g_SO[(size_t)(r0 + rb + 2 * i) * 128 + col] = acc[i] + bias;
}

// ---------------- Score GEMM (128x128 tiles, f32x2) + level-1 histogram of v-bits ----------------
__global__ void __launch_bounds__(256) k_score()
{
    extern __shared__ float sm[];
    float (*Ss)[132] = (float(*)[132])sm;                 // [64][132]
    float (*Os)[132] = (float(*)[132])(sm + 64 * 132);    // [64][132]
    unsigned* hist = (unsigned*)(sm + 2 * 64 * 132);      // [4096]

    const int tid = threadIdx.x;
    const int b  = blockIdx.z;
    const int i0 = blockIdx.y * 128;
    const int j0 = blockIdx.x * 128;

    for (int h = tid; h < 4096; h += 256) hist[h] = 0;

    for (int e = tid; e < 8192; e += 256) {
        int ii = e >> 6;
        int d  = e & 63;
        int gi = i0 + ii;
        int gj = j0 + ii;
        Ss[d][ii] = (gi < NN) ? g_SO[((size_t)(b * NN + gi)) * 128 + d]      : 0.f;
        Os[d][ii] = (gj < NN) ? g_SO[((size_t)(b * NN + gj)) * 128 + 64 + d] : 0.f;
    }
    __syncthreads();

    const int tm = tid >> 4;
    const int tn = tid & 15;

    unsigned long long acc2[4][8];
#pragma unroll
    for (int p = 0; p < 4; p++)
#pragma unroll
        for (int j = 0; j < 8; j++) acc2[p][j] = 0ull;

#pragma unroll 4
    for (int kk = 0; kk < 64; kk++) {
        ulonglong2 a01 = *(const ulonglong2*)(&Ss[kk][tm * 8]);
        ulonglong2 a23 = *(const ulonglong2*)(&Ss[kk][tm * 8 + 4]);
        unsigned long long ap[4] = {a01.x, a01.y, a23.x, a23.y};
        float4 b0 = *(const float4*)(&Os[kk][tn * 8]);
        float4 b1 = *(const float4*)(&Os[kk][tn * 8 + 4]);
        unsigned long long bd[8] = {
            dup2(b0.x), dup2(b0.y), dup2(b0.z), dup2(b0.w),
            dup2(b1.x), dup2(b1.y), dup2(b1.z), dup2(b1.w)};
#pragma unroll
        for (int p = 0; p < 4; p++)
#pragma unroll
            for (int j = 0; j < 8; j++)
                FFMA2(acc2[p][j], ap[p], bd[j]);
    }

    const int gj0 = j0 + tn * 8;
#pragma unroll
    for (int p = 0; p < 4; p++) {
#pragma unroll
        for (int half = 0; half < 2; half++) {
            int gi = i0 + tm * 8 + 2 * p + half;
            if (gi >= NN) continue;
            float vrow[8];
#pragma unroll
            for (int j = 0; j < 8; j++)
                vrow[j] = half ? __uint_as_float((unsigned)(acc2[p][j] >> 32))
                               : __uint_as_float((unsigned)acc2[p][j]);
            float* drow = g_D + ((size_t)b * NN + gi) * NN;
            if (gj0 + 7 < NN) {
                *(float4*)(drow + gj0)     = make_float4(vrow[0], vrow[1], vrow[2], vrow[3]);
                *(float4*)(drow + gj0 + 4) = make_float4(vrow[4], vrow[5], vrow[6], vrow[7]);
#pragma unroll
                for (int j = 0; j < 8; j++) {
                    unsigned u = flip_bits(__float_as_uint(vrow[j]));
                    atomicAdd(&hist[u >> 20], 1u);
                }
            } else {
#pragma unroll
                for (int j = 0; j < 8; j++) {
                    int gj = gj0 + j;
                    if (gj < NN) {
                        drow[gj] = vrow[j];
                        unsigned u = flip_bits(__float_as_uint(vrow[j]));
                        atomicAdd(&hist[u >> 20], 1u);
                    }
                }
            }
        }
    }
    __syncthreads();
    for (int h = tid; h < 4096; h += 256) {
        unsigned c = hist[h];
        if (c) atomicAdd(&g_cnt1[b * 4096 + h], c);
    }
}

// ---------------- threshold finder (descending cumulative over 4096 bins) ----------------
__device__ void find_thresh(const unsigned* __restrict__ hist, unsigned K,
                            int* out_bin, unsigned* out_above)
{
    __shared__ unsigned seg[256];
    __shared__ unsigned scan[256];
    const int t = threadIdx.x;

    unsigned s = 0;
#pragma unroll
    for (int q = 0; q < 16; q++) s += hist[4095 - (t * 16 + q)];
    seg[t] = s;
    scan[t] = s;
    __syncthreads();
    for (int off = 1; off < 256; off <<= 1) {
        unsigned v = (t >= off) ? scan[t - off] : 0u;
        __syncthreads();
        scan[t] += v;
        __syncthreads();
    }
    unsigned inc = scan[t];
    unsigned exc = inc - seg[t];
    if (exc < K && inc >= K) {
        unsigned cum = exc;
        for (int q = 0; q < 16; q++) {
            int bin = 4095 - (t * 16 + q);
            unsigned c = hist[bin];
            if (cum + c >= K) { *out_bin = bin; *out_above = cum; break; }
            cum += c;
        }
    }
}

__global__ void __launch_bounds__(256) k_thresh1()
{
    int b = blockIdx.x;
    find_thresh(g_cnt1 + b * 4096, 64u, &g_b1[b], &g_cntgt1[b]);
}

__global__ void __launch_bounds__(256) k_thresh2()
{
    int b = blockIdx.x;
    unsigned K = 64u - g_cntgt1[b];
    find_thresh(g_cnt2 + b * 4096, K, &g_b2[b], &g_above2[b]);
}

// ---------------- pass 2: compact bin1>B1, level-2 histogram for bin1==B1 (int only) ----------------
__global__ void __launch_bounds__(256) k_pass2()
{
    __shared__ unsigned hist[4096];
    const int b = blockIdx.y;
    const unsigned B1 = (unsigned)g_b1[b];
    for (int h = threadIdx.x; h < 4096; h += 256) hist[h] = 0;
    __syncthreads();

    const uint4* D4 = (const uint4*)(g_D + (size_t)b * NN * NN);
    for (int i = blockIdx.x * 256 + threadIdx.x; i < 250000; i += 64 * 256) {
        uint4 q = D4[i];
        unsigned vb[4] = {q.x, q.y, q.z, q.w};
#pragma unroll
        for (int l = 0; l < 4; l++) {
            unsigned u = flip_bits(vb[l]);
            unsigned bin1 = u >> 20;
            if (bin1 > B1) {
                unsigned idx = atomicAdd(&g_ccnt[b], 1u);
                if (idx < CAP)
                    g_cand[(size_t)b * CAP + idx] =
                        (((unsigned long long)vb[l]) << 32) | (unsigned)(i * 4 + l);
            } else if (bin1 == B1) {
                atomicAdd(&hist[(u >> 8) & 0xFFF], 1u);
            }
        }
    }
    __syncthreads();
    for (int h = threadIdx.x; h < 4096; h += 256) {
        unsigned c = hist[h];
        if (c) atomicAdd(&g_cnt2[b * 4096 + h], c);
    }
}

// ---------------- pass 3: compact bin1==B1 && bin2 >= B2-1 (margin for sigmoid ties) ----------------
__global__ void __launch_bounds__(256) k_pass3()
{
    const int b = blockIdx.y;
    const unsigned B1 = (unsigned)g_b1[b];
    int b2 = g_b2[b] - 1;          // one sub-bin margin
    const unsigned B2m = (b2 < 0) ? 0u : (unsigned)b2;

    const uint4* D4 = (const uint4*)(g_D + (size_t)b * NN * NN);
    for (int i = blockIdx.x * 256 + threadIdx.x; i < 250000; i += 64 * 256) {
        uint4 q = D4[i];
        unsigned vb[4] = {q.x, q.y, q.z, q.w};
#pragma unroll
        for (int l = 0; l < 4; l++) {
            unsigned u = flip_bits(vb[l]);
            if ((u >> 20) == B1 && ((u >> 8) & 0xFFF) >= B2m) {
                unsigned idx = atomicAdd(&g_ccnt[b], 1u);
                if (idx < CAP)
                    g_cand[(size_t)b * CAP + idx] =
                        (((unsigned long long)vb[l]) << 32) | (unsigned)(i * 4 + l);
            }
        }
    }
}

// ---------------- bitonic sort (descending) ----------------
template <int NTOT, int NTHR>
__device__ __forceinline__ void bitonic_desc(unsigned long long* k)
{
    for (int size = 2; size <= NTOT; size <<= 1) {
        for (int stride = size >> 1; stride > 0; stride >>= 1) {
            __syncthreads();
            for (int e = threadIdx.x; e < NTOT / 2; e += NTHR) {
                int i = 2 * e - (e & (stride - 1));
                int j = i + stride;
                bool up = ((i & size) == 0);
                unsigned long long a = k[i], b = k[j];
                bool sw = up ? (a < b) : (a > b);
                if (sw) { k[i] = b; k[j] = a; }
            }
        }
    }
    __syncthreads();
}

// ---------------- final: sigmoid on candidates, sort by (sigmoid, index), output ----------------
__global__ void __launch_bounds__(256) k_sort(float* __restrict__ out)
{
    __shared__ unsigned long long keys[CAP];
    const int tid = threadIdx.x;
    const int b = blockIdx.x;
    unsigned n = g_ccnt[b];
    if (n > CAP) n = CAP;

#pragma unroll
    for (int i = 0; i < CAP / 256; i++) {
        int e = tid + i * 256;
        unsigned long long key = 0ull;
        if (e < (int)n) {
            unsigned long long c = g_cand[(size_t)b * CAP + e];
            float v = __uint_as_float((unsigned)(c >> 32));
            unsigned flat = (unsigned)c;
            key = pack_key(sigmoidf_dev(v), flat);
        }
        keys[e] = key;
    }
    bitonic_desc<CAP, 256>(keys);

    if (tid < 64) {
        unsigned long long key = keys[tid];
        unsigned u = (unsigned)(key >> 32);
        unsigned low = (unsigned)key;
        unsigned flat = 0xFFFFFFFFu - low;
        unsigned bits = (u & 0x80000000u) ? (u ^ 0x80000000u) : ~u;
        float s = __uint_as_float(bits);
        int subj = flat / NN;
        int obj = flat % NN;
        out[(b * TAKE_K + tid) * 2 + 0] = (float)subj;
        out[(b * TAKE_K + tid) * 2 + 1] = (float)obj;
        out[BB * TAKE_K * 2 + b * TAKE_K + tid] = s;
    }
}

// ---------------- zero scratch counters ----------------
__global__ void k_zero()
{
    int t = blockIdx.x * blockDim.x + threadIdx.x;
    if (t < BB * 4096) { g_cnt1[t] = 0; g_cnt2[t] = 0; }
    if (t < BB) g_ccnt[t] = 0;
}

// ---------------- launch ----------------
extern "C" void kernel_launch(void* const* d_in, const int* in_sizes, int n_in,
                              void* d_out, int out_size)
{
    const float* X   = (const float*)d_in[0];
    const float* Ws1 = (const float*)d_in[2];
    const float* bs1 = (const float*)d_in[3];
    const float* Ws2 = (const float*)d_in[4];
    const float* bs2 = (const float*)d_in[5];
    const float* Wo1 = (const float*)d_in[6];
    const float* bo1 = (const float*)d_in[7];
    const float* Wo2 = (const float*)d_in[8];
    const float* bo2 = (const float*)d_in[9];
    float* out = (float*)d_out;

    const int SCORE_SMEM = (2 * 64 * 132) * 4 + 4096 * 4;  // 83968
    static int configured = 0;
    if (!configured) {
        cudaFuncSetAttribute(k_score, cudaFuncAttributeMaxDynamicSharedMemorySize, SCORE_SMEM);
        configured = 1;
    }

    k_zero<<<(BB * 4096 + 255) / 256, 256>>>();
    k_gemm1<<<MM / 128, 256>>>(X, Ws1, bs1, Wo1, bo1);
    k_gemm2<<<MM / 16, 256>>>(Ws2, bs2, Wo2, bo2);
    k_score<<<dim3(8, 8, BB), 256, SCORE_SMEM>>>();
    k_thresh1<<<BB, 256>>>();
    k_pass2<<<dim3(64, BB), 256>>>();
    k_thresh2<<<BB, 256>>>();
    k_pass3<<<dim3(64, BB), 256>>>();
    k_sort<<<BB, 256>>>(out);
}